// round 1
// baseline (speedup 1.0000x reference)
#include <cuda_runtime.h>
#include <math.h>

#define EMBED   1024
#define NHEADS  16
#define HDIM    64
#define BATCH   2
#define QLEN    2048
#define CLEN    2048
#define MROWS   (BATCH * QLEN)   // 4096 rows for all projection GEMMs

// Scratch (allocation-free rule: __device__ globals). 4 x 16MB = 64MB.
__device__ float g_Q[MROWS * EMBED];
__device__ float g_K[BATCH * CLEN * EMBED];
__device__ float g_V[BATCH * CLEN * EMBED];
__device__ float g_A[MROWS * EMBED];

// ---------------------------------------------------------------------------
// SGEMM + bias: C[M,N] = A[M,K] @ W[K,N] + b[N]
// 128x128 tile, BK=8, 256 threads, 8x8 per thread.
// ---------------------------------------------------------------------------
__global__ void __launch_bounds__(256) sgemm_bias_kernel(
    const float* __restrict__ A, const float* __restrict__ W,
    const float* __restrict__ bias, float* __restrict__ C,
    int M, int N, int K)
{
    __shared__ float As[8][132];   // padded: conflict-free transposed stores/reads
    __shared__ float Bs[8][128];

    const int tid = threadIdx.x;
    const int tx  = tid & 15;      // 0..15  -> 8 output cols each
    const int ty  = tid >> 4;      // 0..15  -> 8 output rows each
    const int rowBase = blockIdx.y * 128;
    const int colBase = blockIdx.x * 128;

    const int aRow = tid >> 1;           // 0..127
    const int aCol = (tid & 1) * 4;      // 0 or 4
    const int bRow = tid >> 5;           // 0..7
    const int bCol = (tid & 31) * 4;     // 0..124

    const float* Aptr = A + (size_t)(rowBase + aRow) * K + aCol;
    const float* Wptr = W + (size_t)bRow * N + colBase + bCol;

    float acc[8][8];
    #pragma unroll
    for (int i = 0; i < 8; i++)
        #pragma unroll
        for (int j = 0; j < 8; j++) acc[i][j] = 0.f;

    for (int k0 = 0; k0 < K; k0 += 8) {
        float4 a4 = *(const float4*)(Aptr + k0);
        float4 b4 = *(const float4*)(Wptr + (size_t)k0 * N);
        As[aCol + 0][aRow] = a4.x;
        As[aCol + 1][aRow] = a4.y;
        As[aCol + 2][aRow] = a4.z;
        As[aCol + 3][aRow] = a4.w;
        *(float4*)&Bs[bRow][bCol] = b4;
        __syncthreads();

        #pragma unroll
        for (int kk = 0; kk < 8; kk++) {
            float ra[8], rb[8];
            *(float4*)&ra[0] = *(const float4*)&As[kk][ty * 8];
            *(float4*)&ra[4] = *(const float4*)&As[kk][ty * 8 + 4];
            *(float4*)&rb[0] = *(const float4*)&Bs[kk][tx * 8];
            *(float4*)&rb[4] = *(const float4*)&Bs[kk][tx * 8 + 4];
            #pragma unroll
            for (int i = 0; i < 8; i++)
                #pragma unroll
                for (int j = 0; j < 8; j++)
                    acc[i][j] = fmaf(ra[i], rb[j], acc[i][j]);
        }
        __syncthreads();
    }

    float4 bv0 = *(const float4*)&bias[colBase + tx * 8];
    float4 bv1 = *(const float4*)&bias[colBase + tx * 8 + 4];
    #pragma unroll
    for (int i = 0; i < 8; i++) {
        float* crow = C + (size_t)(rowBase + ty * 8 + i) * N + colBase + tx * 8;
        float4 r0 = make_float4(acc[i][0] + bv0.x, acc[i][1] + bv0.y,
                                acc[i][2] + bv0.z, acc[i][3] + bv0.w);
        float4 r1 = make_float4(acc[i][4] + bv1.x, acc[i][5] + bv1.y,
                                acc[i][6] + bv1.z, acc[i][7] + bv1.w);
        *(float4*)crow       = r0;
        *(float4*)(crow + 4) = r1;
    }
}

// ---------------------------------------------------------------------------
// Flash attention (fp32, exact online softmax).
// Q/K/V stay in [b, seq, h*64+d] layout; each block handles one (b, h, q-tile).
// 64 q-rows x 64 k-cols tiles, 256 threads (16x16), 4x4 per thread.
// ---------------------------------------------------------------------------
#define FP 68   // smem row pitch (floats), padded, 16B-aligned rows

__global__ void __launch_bounds__(256) flash_attn_kernel(
    const float* __restrict__ Qm, const float* __restrict__ Km,
    const float* __restrict__ Vm, float* __restrict__ Om)
{
    extern __shared__ float smem[];
    float* Qs = smem;                 // [64][FP]
    float* Ks = smem + 64 * FP;       // [64][FP]
    float* Vs = smem + 2 * 64 * FP;   // [64][FP]
    float* Ps = smem + 3 * 64 * FP;   // [64][FP]

    const int b  = blockIdx.z;
    const int h  = blockIdx.y;
    const int q0 = blockIdx.x * 64;
    const int tid = threadIdx.x;
    const int tx = tid & 15;
    const int ty = tid >> 4;
    const float scale = 0.125f;   // 1/sqrt(64), folded into Q at load

    const float* Qbase = Qm + ((size_t)b * QLEN) * EMBED + h * HDIM;
    const float* Kbase = Km + ((size_t)b * CLEN) * EMBED + h * HDIM;
    const float* Vbase = Vm + ((size_t)b * CLEN) * EMBED + h * HDIM;

    // Load + pre-scale Q tile
    #pragma unroll
    for (int i = 0; i < 4; i++) {
        int idx = tid + i * 256;
        int r = idx >> 4;
        int c = (idx & 15) * 4;
        float4 v = *(const float4*)&Qbase[(size_t)(q0 + r) * EMBED + c];
        v.x *= scale; v.y *= scale; v.z *= scale; v.w *= scale;
        *(float4*)&Qs[r * FP + c] = v;
    }

    float m_i[4], l_i[4], o[4][4];
    #pragma unroll
    for (int i = 0; i < 4; i++) {
        m_i[i] = -INFINITY;
        l_i[i] = 0.f;
        #pragma unroll
        for (int j = 0; j < 4; j++) o[i][j] = 0.f;
    }

    for (int kt = 0; kt < CLEN / 64; kt++) {
        const int k0r = kt * 64;
        #pragma unroll
        for (int i = 0; i < 4; i++) {
            int idx = tid + i * 256;
            int r = idx >> 4;
            int c = (idx & 15) * 4;
            *(float4*)&Ks[r * FP + c] = *(const float4*)&Kbase[(size_t)(k0r + r) * EMBED + c];
            *(float4*)&Vs[r * FP + c] = *(const float4*)&Vbase[(size_t)(k0r + r) * EMBED + c];
        }
        __syncthreads();

        // S = (scaled Q) K^T for this thread's 4x4 block
        float s[4][4];
        #pragma unroll
        for (int i = 0; i < 4; i++)
            #pragma unroll
            for (int j = 0; j < 4; j++) s[i][j] = 0.f;

        #pragma unroll
        for (int d = 0; d < HDIM; d += 4) {
            float4 qv[4], kv[4];
            #pragma unroll
            for (int i = 0; i < 4; i++) qv[i] = *(const float4*)&Qs[(4 * ty + i) * FP + d];
            #pragma unroll
            for (int j = 0; j < 4; j++) kv[j] = *(const float4*)&Ks[(4 * tx + j) * FP + d];
            #pragma unroll
            for (int i = 0; i < 4; i++)
                #pragma unroll
                for (int j = 0; j < 4; j++) {
                    s[i][j] = fmaf(qv[i].x, kv[j].x, s[i][j]);
                    s[i][j] = fmaf(qv[i].y, kv[j].y, s[i][j]);
                    s[i][j] = fmaf(qv[i].z, kv[j].z, s[i][j]);
                    s[i][j] = fmaf(qv[i].w, kv[j].w, s[i][j]);
                }
        }

        // Online softmax per q-row (row spans 16 tx lanes)
        #pragma unroll
        for (int i = 0; i < 4; i++) {
            float mx = fmaxf(fmaxf(s[i][0], s[i][1]), fmaxf(s[i][2], s[i][3]));
            #pragma unroll
            for (int off = 8; off; off >>= 1)
                mx = fmaxf(mx, __shfl_xor_sync(0xffffffffu, mx, off, 16));
            float mnew = fmaxf(m_i[i], mx);
            float corr = __expf(m_i[i] - mnew);   // 0 on first tile (m_i = -inf)
            float p0 = __expf(s[i][0] - mnew);
            float p1 = __expf(s[i][1] - mnew);
            float p2 = __expf(s[i][2] - mnew);
            float p3 = __expf(s[i][3] - mnew);
            float rs = (p0 + p1) + (p2 + p3);
            #pragma unroll
            for (int off = 8; off; off >>= 1)
                rs += __shfl_xor_sync(0xffffffffu, rs, off, 16);
            l_i[i] = l_i[i] * corr + rs;
            m_i[i] = mnew;
            #pragma unroll
            for (int j = 0; j < 4; j++) o[i][j] *= corr;
            *(float4*)&Ps[(4 * ty + i) * FP + 4 * tx] = make_float4(p0, p1, p2, p3);
        }
        __syncthreads();

        // O += P @ V
        #pragma unroll 8
        for (int kk = 0; kk < 64; kk++) {
            float4 vv = *(const float4*)&Vs[kk * FP + 4 * tx];
            #pragma unroll
            for (int i = 0; i < 4; i++) {
                float pv = Ps[(4 * ty + i) * FP + kk];
                o[i][0] = fmaf(pv, vv.x, o[i][0]);
                o[i][1] = fmaf(pv, vv.y, o[i][1]);
                o[i][2] = fmaf(pv, vv.z, o[i][2]);
                o[i][3] = fmaf(pv, vv.w, o[i][3]);
            }
        }
        __syncthreads();
    }

    // Normalize and write attended in [b, q, h*64+d] layout
    #pragma unroll
    for (int i = 0; i < 4; i++) {
        float inv = 1.f / l_i[i];
        int q = q0 + 4 * ty + i;
        float4 r = make_float4(o[i][0] * inv, o[i][1] * inv,
                               o[i][2] * inv, o[i][3] * inv);
        *(float4*)&Om[((size_t)b * QLEN + q) * EMBED + h * HDIM + 4 * tx] = r;
    }
}

// ---------------------------------------------------------------------------
// Launch: Qproj, Kproj, Vproj, flash-attn, Oproj. All graph-capturable.
// ---------------------------------------------------------------------------
extern "C" void kernel_launch(void* const* d_in, const int* in_sizes, int n_in,
                              void* d_out, int out_size)
{
    const float* query   = (const float*)d_in[0];
    const float* context = (const float*)d_in[1];
    const float* Wq = (const float*)d_in[2];
    const float* bq = (const float*)d_in[3];
    const float* Wk = (const float*)d_in[4];
    const float* bk = (const float*)d_in[5];
    const float* Wv = (const float*)d_in[6];
    const float* bv = (const float*)d_in[7];
    const float* Wo = (const float*)d_in[8];
    const float* bo = (const float*)d_in[9];
    float* out = (float*)d_out;

    float *pQ, *pK, *pV, *pA;
    cudaGetSymbolAddress((void**)&pQ, g_Q);
    cudaGetSymbolAddress((void**)&pK, g_K);
    cudaGetSymbolAddress((void**)&pV, g_V);
    cudaGetSymbolAddress((void**)&pA, g_A);

    dim3 gGemm(EMBED / 128, MROWS / 128);   // (8, 32)
    sgemm_bias_kernel<<<gGemm, 256>>>(query,   Wq, bq, pQ, MROWS, EMBED, EMBED);
    sgemm_bias_kernel<<<gGemm, 256>>>(context, Wk, bk, pK, MROWS, EMBED, EMBED);
    sgemm_bias_kernel<<<gGemm, 256>>>(context, Wv, bv, pV, MROWS, EMBED, EMBED);

    size_t shmem = (size_t)4 * 64 * FP * sizeof(float);   // 69632 B
    cudaFuncSetAttribute(flash_attn_kernel,
                         cudaFuncAttributeMaxDynamicSharedMemorySize, (int)shmem);
    flash_attn_kernel<<<dim3(QLEN / 64, NHEADS, BATCH), 256, shmem>>>(pQ, pK, pV, pA);

    sgemm_bias_kernel<<<gGemm, 256>>>(pA, Wo, bo, out, MROWS, EMBED, EMBED);
}

// round 2
// speedup vs baseline: 3.2854x; 3.2854x over previous
#include <cuda_runtime.h>
#include <math.h>
#include <stdint.h>

#define EMBED   1024
#define NHEADS  16
#define HDIM    64
#define BATCH   2
#define QLEN    2048
#define CLEN    2048
#define MROWS   (BATCH * QLEN)   // 4096

// Scratch (allocation-free rule): 4 x 16MB device globals.
__device__ float g_Q[MROWS * EMBED];
__device__ float g_K[BATCH * CLEN * EMBED];
__device__ float g_V[BATCH * CLEN * EMBED];
__device__ float g_A[MROWS * EMBED];

__device__ __forceinline__ uint32_t f2tf(float x) {
    uint32_t r;
    asm("cvt.rna.tf32.f32 %0, %1;" : "=r"(r) : "f"(x));
    return r;
}

// D += A(16x8) * B(8x8), tf32 inputs, fp32 accum
#define MMA_TF32(d, a, b)                                                  \
    asm volatile(                                                          \
        "mma.sync.aligned.m16n8k8.row.col.f32.tf32.tf32.f32 "              \
        "{%0,%1,%2,%3}, {%4,%5,%6,%7}, {%8,%9}, {%0,%1,%2,%3};"            \
        : "+f"(d[0]), "+f"(d[1]), "+f"(d[2]), "+f"(d[3])                   \
        : "r"(a[0]), "r"(a[1]), "r"(a[2]), "r"(a[3]), "r"(b[0]), "r"(b[1]))

// ---------------------------------------------------------------------------
// tf32 tensor-core GEMM + bias: C[M,N] = A[M,K] @ W[K,N] + b[N]
// 128x128 tile, BK=16 double-buffered, 256 threads (8 warps 4x2),
// warp tile 32x64 (2 mtiles x 8 ntiles of m16n8k8).
// ---------------------------------------------------------------------------
#define PA 136   // smem pitch (u32) for A^T tile: a-frag loads conflict-free
#define PB 136   // smem pitch (u32) for B tile:  b-frag loads conflict-free

__global__ void __launch_bounds__(256) gemm_tf32_kernel(
    const float* __restrict__ A, const float* __restrict__ W,
    const float* __restrict__ bias, float* __restrict__ C,
    int M, int N, int K)
{
    __shared__ uint32_t As[2][16 * PA];   // As[buf][k*PA + m]
    __shared__ uint32_t Bs[2][16 * PB];   // Bs[buf][k*PB + n]

    const int tid  = threadIdx.x;
    const int lane = tid & 31;
    const int warp = tid >> 5;
    const int g    = lane >> 2;   // groupID (0..7)
    const int tg   = lane & 3;    // thread-in-group (0..3)
    const int wr   = (warp >> 1) * 32;   // warp row base (0,32,64,96)
    const int wc   = (warp & 1) * 64;    // warp col base (0,64)
    const int rowBase = blockIdx.y * 128;
    const int colBase = blockIdx.x * 128;
    const int KT = K / 16;

    float acc[2][8][4];
    #pragma unroll
    for (int mt = 0; mt < 2; mt++)
        #pragma unroll
        for (int nt = 0; nt < 8; nt++)
            #pragma unroll
            for (int e = 0; e < 4; e++) acc[mt][nt][e] = 0.f;

    // tile loader: kt-th 16-wide K slab into buffer buf
    auto load_tile = [&](int buf, int kt) {
        #pragma unroll
        for (int i = 0; i < 2; i++) {
            int idx = tid + i * 256;            // 0..511
            int r   = idx >> 2;                 // 0..127 (M row in tile)
            int c4  = (idx & 3) * 4;            // 0,4,8,12 (k col)
            float4 v = *(const float4*)&A[(size_t)(rowBase + r) * K + kt * 16 + c4];
            As[buf][(c4 + 0) * PA + r] = f2tf(v.x);
            As[buf][(c4 + 1) * PA + r] = f2tf(v.y);
            As[buf][(c4 + 2) * PA + r] = f2tf(v.z);
            As[buf][(c4 + 3) * PA + r] = f2tf(v.w);
        }
        #pragma unroll
        for (int i = 0; i < 2; i++) {
            int idx = tid + i * 256;
            int r   = idx >> 5;                 // 0..15 (k row)
            int c4  = (idx & 31) * 4;           // 0..124 (N col)
            float4 v = *(const float4*)&W[(size_t)(kt * 16 + r) * N + colBase + c4];
            Bs[buf][r * PB + c4 + 0] = f2tf(v.x);
            Bs[buf][r * PB + c4 + 1] = f2tf(v.y);
            Bs[buf][r * PB + c4 + 2] = f2tf(v.z);
            Bs[buf][r * PB + c4 + 3] = f2tf(v.w);
        }
    };

    load_tile(0, 0);
    __syncthreads();

    int buf = 0;
    for (int kt = 0; kt < KT; kt++) {
        if (kt + 1 < KT) load_tile(buf ^ 1, kt + 1);

        #pragma unroll
        for (int ks = 0; ks < 2; ks++) {
            const int kb = ks * 8;
            uint32_t a[2][4];
            #pragma unroll
            for (int mt = 0; mt < 2; mt++) {
                int m = wr + mt * 16 + g;
                a[mt][0] = As[buf][(kb + tg) * PA + m];
                a[mt][1] = As[buf][(kb + tg) * PA + m + 8];
                a[mt][2] = As[buf][(kb + tg + 4) * PA + m];
                a[mt][3] = As[buf][(kb + tg + 4) * PA + m + 8];
            }
            #pragma unroll
            for (int nt = 0; nt < 8; nt++) {
                uint32_t b[2];
                int n = wc + nt * 8 + g;
                b[0] = Bs[buf][(kb + tg) * PB + n];
                b[1] = Bs[buf][(kb + tg + 4) * PB + n];
                MMA_TF32(acc[0][nt], a[0], b);
                MMA_TF32(acc[1][nt], a[1], b);
            }
        }
        __syncthreads();
        buf ^= 1;
    }

    // epilogue: bias + store (float2 per fragment row)
    #pragma unroll
    for (int mt = 0; mt < 2; mt++) {
        #pragma unroll
        for (int nt = 0; nt < 8; nt++) {
            int row = rowBase + wr + mt * 16 + g;
            int col = colBase + wc + nt * 8 + 2 * tg;
            float2 bv = *(const float2*)&bias[col];
            float2 r0 = make_float2(acc[mt][nt][0] + bv.x, acc[mt][nt][1] + bv.y);
            float2 r1 = make_float2(acc[mt][nt][2] + bv.x, acc[mt][nt][3] + bv.y);
            *(float2*)&C[(size_t)row * N + col]       = r0;
            *(float2*)&C[(size_t)(row + 8) * N + col] = r1;
        }
    }
}

// ---------------------------------------------------------------------------
// Flash attention with tf32 mma. 64 q-rows per block, K tiles of 64.
// 128 threads = 4 warps; each warp owns 16 q-rows.
// Q pre-scaled by 1/8. P routed through smem to re-fragment for PV.
// ---------------------------------------------------------------------------
#define FPW 68   // smem pitch (u32): conflict-free fragment loads

__global__ void __launch_bounds__(128) flash_mma_kernel(
    const float* __restrict__ Qm, const float* __restrict__ Km,
    const float* __restrict__ Vm, float* __restrict__ Om)
{
    extern __shared__ uint32_t sm[];
    uint32_t* Qs = sm;                  // [64][FPW]  Q[m][d]  (tf32)
    uint32_t* Ks = sm + 64 * FPW;       // [64][FPW]  K[n][d]
    uint32_t* Vs = sm + 2 * 64 * FPW;   // [64][FPW]  V[k][d]
    uint32_t* Ps = sm + 3 * 64 * FPW;   // [64][FPW]  P[m][k]

    const int b  = blockIdx.z;
    const int h  = blockIdx.y;
    const int q0 = blockIdx.x * 64;
    const int tid  = threadIdx.x;
    const int lane = tid & 31;
    const int warp = tid >> 5;          // 0..3
    const int g  = lane >> 2;
    const int tg = lane & 3;
    const int mrow = warp * 16;         // warp's q-row base within tile
    const float scale = 0.125f;

    const float* Qbase = Qm + ((size_t)b * QLEN) * EMBED + h * HDIM;
    const float* Kbase = Km + ((size_t)b * CLEN) * EMBED + h * HDIM;
    const float* Vbase = Vm + ((size_t)b * CLEN) * EMBED + h * HDIM;

    // load + scale + convert Q tile: 64x64
    #pragma unroll
    for (int i = 0; i < 8; i++) {
        int idx = tid + i * 128;
        int r = idx >> 4;
        int c = (idx & 15) * 4;
        float4 v = *(const float4*)&Qbase[(size_t)(q0 + r) * EMBED + c];
        Qs[r * FPW + c + 0] = f2tf(v.x * scale);
        Qs[r * FPW + c + 1] = f2tf(v.y * scale);
        Qs[r * FPW + c + 2] = f2tf(v.z * scale);
        Qs[r * FPW + c + 3] = f2tf(v.w * scale);
    }

    float m0 = -INFINITY, m1 = -INFINITY, l0 = 0.f, l1 = 0.f;
    float o[8][4];
    #pragma unroll
    for (int nt = 0; nt < 8; nt++)
        #pragma unroll
        for (int e = 0; e < 4; e++) o[nt][e] = 0.f;

    for (int kt = 0; kt < CLEN / 64; kt++) {
        __syncthreads();   // all warps done reading Ks/Vs (covers Qs on iter 0)
        const int k0r = kt * 64;
        #pragma unroll
        for (int i = 0; i < 8; i++) {
            int idx = tid + i * 128;
            int r = idx >> 4;
            int c = (idx & 15) * 4;
            float4 kv = *(const float4*)&Kbase[(size_t)(k0r + r) * EMBED + c];
            float4 vv = *(const float4*)&Vbase[(size_t)(k0r + r) * EMBED + c];
            Ks[r * FPW + c + 0] = f2tf(kv.x);
            Ks[r * FPW + c + 1] = f2tf(kv.y);
            Ks[r * FPW + c + 2] = f2tf(kv.z);
            Ks[r * FPW + c + 3] = f2tf(kv.w);
            Vs[r * FPW + c + 0] = f2tf(vv.x);
            Vs[r * FPW + c + 1] = f2tf(vv.y);
            Vs[r * FPW + c + 2] = f2tf(vv.z);
            Vs[r * FPW + c + 3] = f2tf(vv.w);
        }
        __syncthreads();

        // ---- S = Q K^T : warp's 16x64 tile ----
        float sacc[8][4];
        #pragma unroll
        for (int nt = 0; nt < 8; nt++)
            #pragma unroll
            for (int e = 0; e < 4; e++) sacc[nt][e] = 0.f;

        #pragma unroll
        for (int ks = 0; ks < 8; ks++) {
            const int kb = ks * 8;
            uint32_t a[4];
            a[0] = Qs[(mrow + g) * FPW + kb + tg];
            a[1] = Qs[(mrow + g + 8) * FPW + kb + tg];
            a[2] = Qs[(mrow + g) * FPW + kb + tg + 4];
            a[3] = Qs[(mrow + g + 8) * FPW + kb + tg + 4];
            #pragma unroll
            for (int nt = 0; nt < 8; nt++) {
                uint32_t bfr[2];
                bfr[0] = Ks[(nt * 8 + g) * FPW + kb + tg];
                bfr[1] = Ks[(nt * 8 + g) * FPW + kb + tg + 4];
                MMA_TF32(sacc[nt], a, bfr);
            }
        }

        // ---- online softmax (rows g and g+8 of warp tile) ----
        float mx0 = -INFINITY, mx1 = -INFINITY;
        #pragma unroll
        for (int nt = 0; nt < 8; nt++) {
            mx0 = fmaxf(mx0, fmaxf(sacc[nt][0], sacc[nt][1]));
            mx1 = fmaxf(mx1, fmaxf(sacc[nt][2], sacc[nt][3]));
        }
        #pragma unroll
        for (int off = 1; off < 4; off <<= 1) {
            mx0 = fmaxf(mx0, __shfl_xor_sync(0xffffffffu, mx0, off));
            mx1 = fmaxf(mx1, __shfl_xor_sync(0xffffffffu, mx1, off));
        }
        float mn0 = fmaxf(m0, mx0), mn1 = fmaxf(m1, mx1);
        float c0 = __expf(m0 - mn0), c1 = __expf(m1 - mn1);

        float rs0 = 0.f, rs1 = 0.f;
        #pragma unroll
        for (int nt = 0; nt < 8; nt++) {
            float p00 = __expf(sacc[nt][0] - mn0);
            float p01 = __expf(sacc[nt][1] - mn0);
            float p10 = __expf(sacc[nt][2] - mn1);
            float p11 = __expf(sacc[nt][3] - mn1);
            rs0 += p00 + p01;
            rs1 += p10 + p11;
            int col = nt * 8 + 2 * tg;
            Ps[(mrow + g) * FPW + col]         = f2tf(p00);
            Ps[(mrow + g) * FPW + col + 1]     = f2tf(p01);
            Ps[(mrow + g + 8) * FPW + col]     = f2tf(p10);
            Ps[(mrow + g + 8) * FPW + col + 1] = f2tf(p11);
        }
        #pragma unroll
        for (int off = 1; off < 4; off <<= 1) {
            rs0 += __shfl_xor_sync(0xffffffffu, rs0, off);
            rs1 += __shfl_xor_sync(0xffffffffu, rs1, off);
        }
        l0 = l0 * c0 + rs0;
        l1 = l1 * c1 + rs1;
        m0 = mn0; m1 = mn1;
        #pragma unroll
        for (int nt = 0; nt < 8; nt++) {
            o[nt][0] *= c0; o[nt][1] *= c0;
            o[nt][2] *= c1; o[nt][3] *= c1;
        }
        __syncwarp();   // Ps visible within warp

        // ---- O += P V : 16x64 += 16x64 * 64x64 ----
        #pragma unroll
        for (int ks = 0; ks < 8; ks++) {
            const int kb = ks * 8;
            uint32_t a[4];
            a[0] = Ps[(mrow + g) * FPW + kb + tg];
            a[1] = Ps[(mrow + g + 8) * FPW + kb + tg];
            a[2] = Ps[(mrow + g) * FPW + kb + tg + 4];
            a[3] = Ps[(mrow + g + 8) * FPW + kb + tg + 4];
            #pragma unroll
            for (int nt = 0; nt < 8; nt++) {
                uint32_t bfr[2];
                bfr[0] = Vs[(kb + tg) * FPW + nt * 8 + g];
                bfr[1] = Vs[(kb + tg + 4) * FPW + nt * 8 + g];
                MMA_TF32(o[nt], a, bfr);
            }
        }
    }

    // normalize + write: rows q0+mrow+g and q0+mrow+g+8
    float i0 = 1.f / l0, i1 = 1.f / l1;
    #pragma unroll
    for (int nt = 0; nt < 8; nt++) {
        int col = h * HDIM + nt * 8 + 2 * tg;
        int r0 = q0 + mrow + g;
        float2 w0 = make_float2(o[nt][0] * i0, o[nt][1] * i0);
        float2 w1 = make_float2(o[nt][2] * i1, o[nt][3] * i1);
        *(float2*)&Om[((size_t)b * QLEN + r0) * EMBED + col]     = w0;
        *(float2*)&Om[((size_t)b * QLEN + r0 + 8) * EMBED + col] = w1;
    }
}

// ---------------------------------------------------------------------------
extern "C" void kernel_launch(void* const* d_in, const int* in_sizes, int n_in,
                              void* d_out, int out_size)
{
    const float* query   = (const float*)d_in[0];
    const float* context = (const float*)d_in[1];
    const float* Wq = (const float*)d_in[2];
    const float* bq = (const float*)d_in[3];
    const float* Wk = (const float*)d_in[4];
    const float* bk = (const float*)d_in[5];
    const float* Wv = (const float*)d_in[6];
    const float* bv = (const float*)d_in[7];
    const float* Wo = (const float*)d_in[8];
    const float* bo = (const float*)d_in[9];
    float* out = (float*)d_out;

    float *pQ, *pK, *pV, *pA;
    cudaGetSymbolAddress((void**)&pQ, g_Q);
    cudaGetSymbolAddress((void**)&pK, g_K);
    cudaGetSymbolAddress((void**)&pV, g_V);
    cudaGetSymbolAddress((void**)&pA, g_A);

    dim3 gGemm(EMBED / 128, MROWS / 128);   // (8, 32)
    gemm_tf32_kernel<<<gGemm, 256>>>(query,   Wq, bq, pQ, MROWS, EMBED, EMBED);
    gemm_tf32_kernel<<<gGemm, 256>>>(context, Wk, bk, pK, MROWS, EMBED, EMBED);
    gemm_tf32_kernel<<<gGemm, 256>>>(context, Wv, bv, pV, MROWS, EMBED, EMBED);

    size_t shmem = (size_t)4 * 64 * FPW * sizeof(uint32_t);   // 69632 B
    cudaFuncSetAttribute(flash_mma_kernel,
                         cudaFuncAttributeMaxDynamicSharedMemorySize, (int)shmem);
    flash_mma_kernel<<<dim3(QLEN / 64, NHEADS, BATCH), 128, shmem>>>(pQ, pK, pV, pA);

    gemm_tf32_kernel<<<gGemm, 256>>>(pA, Wo, bo, out, MROWS, EMBED, EMBED);
}

// round 3
// speedup vs baseline: 4.0828x; 1.2427x over previous
#include <cuda_runtime.h>
#include <math.h>
#include <stdint.h>

#define EMBED   1024
#define NHEADS  16
#define HDIM    64
#define BATCH   2
#define QLEN    2048
#define CLEN    2048
#define MROWS   (BATCH * QLEN)   // 4096

__device__ float g_Q[MROWS * EMBED];
__device__ float g_K[BATCH * CLEN * EMBED];
__device__ float g_V[BATCH * CLEN * EMBED];
__device__ float g_A[MROWS * EMBED];

__device__ __forceinline__ uint32_t f2tf(float x) {
    uint32_t r;
    asm("cvt.rna.tf32.f32 %0, %1;" : "=r"(r) : "f"(x));
    return r;
}

#define MMA_TF32(d, a, b)                                                  \
    asm volatile(                                                          \
        "mma.sync.aligned.m16n8k8.row.col.f32.tf32.tf32.f32 "              \
        "{%0,%1,%2,%3}, {%4,%5,%6,%7}, {%8,%9}, {%0,%1,%2,%3};"            \
        : "+f"(d[0]), "+f"(d[1]), "+f"(d[2]), "+f"(d[3])                   \
        : "r"(a[0]), "r"(a[1]), "r"(a[2]), "r"(a[3]), "r"(b[0]), "r"(b[1]))

// ---------------------------------------------------------------------------
// tf32 GEMM + bias: C[M,N] = A[M,K] @ W[K,N] + b[N]
// 128x128 tile, BK=16, software-pipelined LDG/STS, 256 threads (8 warps),
// warp tile 32x64.
// ---------------------------------------------------------------------------
#define PA2 20    // A smem pitch (row-major [m][k]): conflict-free frag loads
#define PB  136   // B smem pitch

__global__ void __launch_bounds__(256) gemm_tf32_kernel(
    const float* __restrict__ A, const float* __restrict__ W,
    const float* __restrict__ bias, float* __restrict__ C,
    int M, int N, int K)
{
    __shared__ uint32_t As[2][128 * PA2];   // As[buf][m*PA2 + k]
    __shared__ uint32_t Bs[2][16 * PB];     // Bs[buf][k*PB + n]

    const int tid  = threadIdx.x;
    const int lane = tid & 31;
    const int warp = tid >> 5;
    const int g    = lane >> 2;
    const int tg   = lane & 3;
    const int wr   = (warp >> 1) * 32;
    const int wc   = (warp & 1) * 64;
    const int rowBase = blockIdx.y * 128;
    const int colBase = blockIdx.x * 128;
    const int KT = K / 16;

    const int ar = tid >> 2;          // 0..63 (A row; +64 for second)
    const int ac = (tid & 3) * 4;     // 0,4,8,12
    const int br = tid >> 5;          // 0..7  (B k-row; +8 for second)
    const int bc = (tid & 31) * 4;    // 0..124

    const float* Aptr = A + (size_t)(rowBase + ar) * K + ac;
    const float* Wptr = W + (size_t)br * N + colBase + bc;

    float acc[2][8][4];
    #pragma unroll
    for (int mt = 0; mt < 2; mt++)
        #pragma unroll
        for (int nt = 0; nt < 8; nt++)
            #pragma unroll
            for (int e = 0; e < 4; e++) acc[mt][nt][e] = 0.f;

    float4 pa0, pa1, pb0, pb1;
    auto ldg = [&](int kt) {
        pa0 = *(const float4*)(Aptr + kt * 16);
        pa1 = *(const float4*)(Aptr + (size_t)64 * K + kt * 16);
        pb0 = *(const float4*)(Wptr + (size_t)(kt * 16) * N);
        pb1 = *(const float4*)(Wptr + (size_t)(kt * 16 + 8) * N);
    };
    auto sts = [&](int buf) {
        uint4 a0 = make_uint4(f2tf(pa0.x), f2tf(pa0.y), f2tf(pa0.z), f2tf(pa0.w));
        uint4 a1 = make_uint4(f2tf(pa1.x), f2tf(pa1.y), f2tf(pa1.z), f2tf(pa1.w));
        uint4 b0 = make_uint4(f2tf(pb0.x), f2tf(pb0.y), f2tf(pb0.z), f2tf(pb0.w));
        uint4 b1 = make_uint4(f2tf(pb1.x), f2tf(pb1.y), f2tf(pb1.z), f2tf(pb1.w));
        *(uint4*)&As[buf][ar * PA2 + ac]        = a0;
        *(uint4*)&As[buf][(ar + 64) * PA2 + ac] = a1;
        *(uint4*)&Bs[buf][br * PB + bc]         = b0;
        *(uint4*)&Bs[buf][(br + 8) * PB + bc]   = b1;
    };

    ldg(0);
    sts(0);
    __syncthreads();

    int buf = 0;
    for (int kt = 0; kt < KT; kt++) {
        if (kt + 1 < KT) ldg(kt + 1);

        #pragma unroll
        for (int ks = 0; ks < 2; ks++) {
            const int kb = ks * 8;
            uint32_t a[2][4];
            #pragma unroll
            for (int mt = 0; mt < 2; mt++) {
                int m = wr + mt * 16 + g;
                a[mt][0] = As[buf][m * PA2 + kb + tg];
                a[mt][1] = As[buf][(m + 8) * PA2 + kb + tg];
                a[mt][2] = As[buf][m * PA2 + kb + tg + 4];
                a[mt][3] = As[buf][(m + 8) * PA2 + kb + tg + 4];
            }
            #pragma unroll
            for (int nt = 0; nt < 8; nt++) {
                uint32_t b[2];
                int n = wc + nt * 8 + g;
                b[0] = Bs[buf][(kb + tg) * PB + n];
                b[1] = Bs[buf][(kb + tg + 4) * PB + n];
                MMA_TF32(acc[0][nt], a[0], b);
                MMA_TF32(acc[1][nt], a[1], b);
            }
        }
        if (kt + 1 < KT) sts(buf ^ 1);
        __syncthreads();
        buf ^= 1;
    }

    #pragma unroll
    for (int mt = 0; mt < 2; mt++) {
        #pragma unroll
        for (int nt = 0; nt < 8; nt++) {
            int row = rowBase + wr + mt * 16 + g;
            int col = colBase + wc + nt * 8 + 2 * tg;
            float2 bv = *(const float2*)&bias[col];
            float2 r0 = make_float2(acc[mt][nt][0] + bv.x, acc[mt][nt][1] + bv.y);
            float2 r1 = make_float2(acc[mt][nt][2] + bv.x, acc[mt][nt][3] + bv.y);
            *(float2*)&C[(size_t)row * N + col]       = r0;
            *(float2*)&C[(size_t)(row + 8) * N + col] = r1;
        }
    }
}

// ---------------------------------------------------------------------------
// Flash attention, tf32 mma. q-tile 128 rows, 4 warps (32 rows each, mt=2),
// Q fragments held in registers across the whole kt loop.
// ---------------------------------------------------------------------------
#define FPW 68

__global__ void __launch_bounds__(128) flash_mma_kernel(
    const float* __restrict__ Qm, const float* __restrict__ Km,
    const float* __restrict__ Vm, float* __restrict__ Om)
{
    extern __shared__ uint32_t sm[];
    uint32_t* Ks = sm;                  // [64][FPW]   K[n][d]
    uint32_t* Vs = sm + 64 * FPW;       // [64][FPW]   V[k][d]
    uint32_t* Ps = sm + 2 * 64 * FPW;   // [128][FPW]  P[m][k] (Q staging first)

    const int b  = blockIdx.z;
    const int h  = blockIdx.y;
    const int q0 = blockIdx.x * 128;
    const int tid  = threadIdx.x;
    const int lane = tid & 31;
    const int warp = tid >> 5;          // 0..3
    const int g    = lane >> 2;
    const int tg   = lane & 3;
    const int mrow = warp * 32;
    const float scale = 0.125f;

    const float* Qbase = Qm + ((size_t)b * QLEN) * EMBED + h * HDIM;
    const float* Kbase = Km + ((size_t)b * CLEN) * EMBED + h * HDIM;
    const float* Vbase = Vm + ((size_t)b * CLEN) * EMBED + h * HDIM;

    // Stage Q tile (128x64, scaled, tf32) in Ps
    #pragma unroll
    for (int i = 0; i < 16; i++) {
        int idx = tid + i * 128;
        int r = idx >> 4;
        int c = (idx & 15) * 4;
        float4 v = *(const float4*)&Qbase[(size_t)(q0 + r) * EMBED + c];
        uint4 t = make_uint4(f2tf(v.x * scale), f2tf(v.y * scale),
                             f2tf(v.z * scale), f2tf(v.w * scale));
        *(uint4*)&Ps[r * FPW + c] = t;
    }
    __syncthreads();

    // Q fragments -> registers (persist across kt loop)
    uint32_t qf[2][8][4];
    #pragma unroll
    for (int mt = 0; mt < 2; mt++) {
        int m = mrow + mt * 16 + g;
        #pragma unroll
        for (int ks = 0; ks < 8; ks++) {
            int kb = ks * 8;
            qf[mt][ks][0] = Ps[m * FPW + kb + tg];
            qf[mt][ks][1] = Ps[(m + 8) * FPW + kb + tg];
            qf[mt][ks][2] = Ps[m * FPW + kb + tg + 4];
            qf[mt][ks][3] = Ps[(m + 8) * FPW + kb + tg + 4];
        }
    }

    float m_[4], l_[4];
    #pragma unroll
    for (int i = 0; i < 4; i++) { m_[i] = -INFINITY; l_[i] = 0.f; }
    float o[2][8][4];
    #pragma unroll
    for (int mt = 0; mt < 2; mt++)
        #pragma unroll
        for (int nt = 0; nt < 8; nt++)
            #pragma unroll
            for (int e = 0; e < 4; e++) o[mt][nt][e] = 0.f;

    for (int kt = 0; kt < CLEN / 64; kt++) {
        __syncthreads();   // prior Ks/Vs reads done (and Q frag loads on iter 0)
        const int k0r = kt * 64;
        #pragma unroll
        for (int i = 0; i < 8; i++) {
            int idx = tid + i * 128;
            int r = idx >> 4;
            int c = (idx & 15) * 4;
            float4 kv = *(const float4*)&Kbase[(size_t)(k0r + r) * EMBED + c];
            float4 vv = *(const float4*)&Vbase[(size_t)(k0r + r) * EMBED + c];
            uint4 kc = make_uint4(f2tf(kv.x), f2tf(kv.y), f2tf(kv.z), f2tf(kv.w));
            uint4 vc = make_uint4(f2tf(vv.x), f2tf(vv.y), f2tf(vv.z), f2tf(vv.w));
            *(uint4*)&Ks[r * FPW + c] = kc;
            *(uint4*)&Vs[r * FPW + c] = vc;
        }
        __syncthreads();

        // ---- S = Q K^T : warp's 32x64 tile ----
        float sacc[2][8][4];
        #pragma unroll
        for (int mt = 0; mt < 2; mt++)
            #pragma unroll
            for (int nt = 0; nt < 8; nt++)
                #pragma unroll
                for (int e = 0; e < 4; e++) sacc[mt][nt][e] = 0.f;

        #pragma unroll
        for (int ks = 0; ks < 8; ks++) {
            const int kb = ks * 8;
            #pragma unroll
            for (int nt = 0; nt < 8; nt++) {
                uint32_t bf[2];
                bf[0] = Ks[(nt * 8 + g) * FPW + kb + tg];
                bf[1] = Ks[(nt * 8 + g) * FPW + kb + tg + 4];
                MMA_TF32(sacc[0][nt], qf[0][ks], bf);
                MMA_TF32(sacc[1][nt], qf[1][ks], bf);
            }
        }

        // ---- online softmax ----
        #pragma unroll
        for (int mt = 0; mt < 2; mt++) {
            float mx0 = -INFINITY, mx1 = -INFINITY;
            #pragma unroll
            for (int nt = 0; nt < 8; nt++) {
                mx0 = fmaxf(mx0, fmaxf(sacc[mt][nt][0], sacc[mt][nt][1]));
                mx1 = fmaxf(mx1, fmaxf(sacc[mt][nt][2], sacc[mt][nt][3]));
            }
            #pragma unroll
            for (int off = 1; off < 4; off <<= 1) {
                mx0 = fmaxf(mx0, __shfl_xor_sync(0xffffffffu, mx0, off));
                mx1 = fmaxf(mx1, __shfl_xor_sync(0xffffffffu, mx1, off));
            }
            float mn0 = fmaxf(m_[2 * mt],     mx0);
            float mn1 = fmaxf(m_[2 * mt + 1], mx1);
            float c0 = __expf(m_[2 * mt]     - mn0);
            float c1 = __expf(m_[2 * mt + 1] - mn1);

            float rs0 = 0.f, rs1 = 0.f;
            int m = mrow + mt * 16 + g;
            #pragma unroll
            for (int nt = 0; nt < 8; nt++) {
                float p00 = __expf(sacc[mt][nt][0] - mn0);
                float p01 = __expf(sacc[mt][nt][1] - mn0);
                float p10 = __expf(sacc[mt][nt][2] - mn1);
                float p11 = __expf(sacc[mt][nt][3] - mn1);
                rs0 += p00 + p01;
                rs1 += p10 + p11;
                int col = nt * 8 + 2 * tg;
                *(uint2*)&Ps[m * FPW + col]       = make_uint2(f2tf(p00), f2tf(p01));
                *(uint2*)&Ps[(m + 8) * FPW + col] = make_uint2(f2tf(p10), f2tf(p11));
            }
            #pragma unroll
            for (int off = 1; off < 4; off <<= 1) {
                rs0 += __shfl_xor_sync(0xffffffffu, rs0, off);
                rs1 += __shfl_xor_sync(0xffffffffu, rs1, off);
            }
            l_[2 * mt]     = l_[2 * mt]     * c0 + rs0;
            l_[2 * mt + 1] = l_[2 * mt + 1] * c1 + rs1;
            m_[2 * mt]     = mn0;
            m_[2 * mt + 1] = mn1;
            #pragma unroll
            for (int nt = 0; nt < 8; nt++) {
                o[mt][nt][0] *= c0; o[mt][nt][1] *= c0;
                o[mt][nt][2] *= c1; o[mt][nt][3] *= c1;
            }
        }
        __syncwarp();   // own P rows visible within warp

        // ---- O += P V ----
        #pragma unroll
        for (int ks = 0; ks < 8; ks++) {
            const int kb = ks * 8;
            uint32_t af[2][4];
            #pragma unroll
            for (int mt = 0; mt < 2; mt++) {
                int m = mrow + mt * 16 + g;
                af[mt][0] = Ps[m * FPW + kb + tg];
                af[mt][1] = Ps[(m + 8) * FPW + kb + tg];
                af[mt][2] = Ps[m * FPW + kb + tg + 4];
                af[mt][3] = Ps[(m + 8) * FPW + kb + tg + 4];
            }
            #pragma unroll
            for (int nt = 0; nt < 8; nt++) {
                uint32_t bf[2];
                bf[0] = Vs[(kb + tg) * FPW + nt * 8 + g];
                bf[1] = Vs[(kb + tg + 4) * FPW + nt * 8 + g];
                MMA_TF32(o[0][nt], af[0], bf);
                MMA_TF32(o[1][nt], af[1], bf);
            }
        }
    }

    // normalize + write
    #pragma unroll
    for (int mt = 0; mt < 2; mt++) {
        float i0 = 1.f / l_[2 * mt];
        float i1 = 1.f / l_[2 * mt + 1];
        int r0 = q0 + mrow + mt * 16 + g;
        #pragma unroll
        for (int nt = 0; nt < 8; nt++) {
            int col = h * HDIM + nt * 8 + 2 * tg;
            float2 w0 = make_float2(o[mt][nt][0] * i0, o[mt][nt][1] * i0);
            float2 w1 = make_float2(o[mt][nt][2] * i1, o[mt][nt][3] * i1);
            *(float2*)&Om[((size_t)b * QLEN + r0) * EMBED + col]     = w0;
            *(float2*)&Om[((size_t)b * QLEN + r0 + 8) * EMBED + col] = w1;
        }
    }
}

// ---------------------------------------------------------------------------
extern "C" void kernel_launch(void* const* d_in, const int* in_sizes, int n_in,
                              void* d_out, int out_size)
{
    const float* query   = (const float*)d_in[0];
    const float* context = (const float*)d_in[1];
    const float* Wq = (const float*)d_in[2];
    const float* bq = (const float*)d_in[3];
    const float* Wk = (const float*)d_in[4];
    const float* bk = (const float*)d_in[5];
    const float* Wv = (const float*)d_in[6];
    const float* bv = (const float*)d_in[7];
    const float* Wo = (const float*)d_in[8];
    const float* bo = (const float*)d_in[9];
    float* out = (float*)d_out;

    float *pQ, *pK, *pV, *pA;
    cudaGetSymbolAddress((void**)&pQ, g_Q);
    cudaGetSymbolAddress((void**)&pK, g_K);
    cudaGetSymbolAddress((void**)&pV, g_V);
    cudaGetSymbolAddress((void**)&pA, g_A);

    dim3 gGemm(EMBED / 128, MROWS / 128);   // (8, 32)
    gemm_tf32_kernel<<<gGemm, 256>>>(query,   Wq, bq, pQ, MROWS, EMBED, EMBED);
    gemm_tf32_kernel<<<gGemm, 256>>>(context, Wk, bk, pK, MROWS, EMBED, EMBED);
    gemm_tf32_kernel<<<gGemm, 256>>>(context, Wv, bv, pV, MROWS, EMBED, EMBED);

    size_t shmem = (size_t)(64 + 64 + 128) * FPW * sizeof(uint32_t);   // 69632 B
    cudaFuncSetAttribute(flash_mma_kernel,
                         cudaFuncAttributeMaxDynamicSharedMemorySize, (int)shmem);
    flash_mma_kernel<<<dim3(QLEN / 128, NHEADS, BATCH), 128, shmem>>>(pQ, pK, pV, pA);

    gemm_tf32_kernel<<<gGemm, 256>>>(pA, Wo, bo, out, MROWS, EMBED, EMBED);
}

// round 5
// speedup vs baseline: 4.3561x; 1.0669x over previous
#include <cuda_runtime.h>
#include <math.h>
#include <stdint.h>

#define EMBED   1024
#define NHEADS  16
#define HDIM    64
#define BATCH   2
#define QLEN    2048
#define CLEN    2048
#define MROWS   (BATCH * QLEN)   // 4096

__device__ float g_Q[MROWS * EMBED];
__device__ float g_K[BATCH * CLEN * EMBED];
__device__ float g_V[BATCH * CLEN * EMBED];
__device__ float g_A[MROWS * EMBED];

__device__ __forceinline__ uint32_t f2tf(float x) {
    uint32_t r;
    asm("cvt.rna.tf32.f32 %0, %1;" : "=r"(r) : "f"(x));
    return r;
}

#define MMA_TF32(d, a, b)                                                  \
    asm volatile(                                                          \
        "mma.sync.aligned.m16n8k8.row.col.f32.tf32.tf32.f32 "              \
        "{%0,%1,%2,%3}, {%4,%5,%6,%7}, {%8,%9}, {%0,%1,%2,%3};"            \
        : "+f"(d[0]), "+f"(d[1]), "+f"(d[2]), "+f"(d[3])                   \
        : "r"(a[0]), "r"(a[1]), "r"(a[2]), "r"(a[3]), "r"(b[0]), "r"(b[1]))

// ---------------------------------------------------------------------------
// tf32 GEMM + bias body: C[4096,1024] = A[4096,1024] @ W[1024,1024] + b
// 128x128 tile, BK=16 double-buffered, 256 threads, warp tile 32x64.
// ---------------------------------------------------------------------------
#define PA2 20
#define PB  136

__device__ __forceinline__ void gemm_body(
    const float* __restrict__ A, const float* __restrict__ W,
    const float* __restrict__ bias, float* __restrict__ C,
    int bx, int by)
{
    constexpr int M = MROWS, N = EMBED, K = EMBED;
    __shared__ uint32_t As[2][128 * PA2];
    __shared__ uint32_t Bs[2][16 * PB];

    const int tid  = threadIdx.x;
    const int lane = tid & 31;
    const int warp = tid >> 5;
    const int g    = lane >> 2;
    const int tg   = lane & 3;
    const int wr   = (warp >> 1) * 32;
    const int wc   = (warp & 1) * 64;
    const int rowBase = by * 128;
    const int colBase = bx * 128;
    const int KT = K / 16;

    const int ar = tid >> 2;
    const int ac = (tid & 3) * 4;
    const int br = tid >> 5;
    const int bc = (tid & 31) * 4;

    const float* Aptr = A + (size_t)(rowBase + ar) * K + ac;
    const float* Wptr = W + (size_t)br * N + colBase + bc;

    float acc[2][8][4];
    #pragma unroll
    for (int mt = 0; mt < 2; mt++)
        #pragma unroll
        for (int nt = 0; nt < 8; nt++)
            #pragma unroll
            for (int e = 0; e < 4; e++) acc[mt][nt][e] = 0.f;

    float4 pa0, pa1, pb0, pb1;
    auto ldg = [&](int kt) {
        pa0 = *(const float4*)(Aptr + kt * 16);
        pa1 = *(const float4*)(Aptr + (size_t)64 * K + kt * 16);
        pb0 = *(const float4*)(Wptr + (size_t)(kt * 16) * N);
        pb1 = *(const float4*)(Wptr + (size_t)(kt * 16 + 8) * N);
    };
    auto sts = [&](int buf) {
        uint4 a0 = make_uint4(f2tf(pa0.x), f2tf(pa0.y), f2tf(pa0.z), f2tf(pa0.w));
        uint4 a1 = make_uint4(f2tf(pa1.x), f2tf(pa1.y), f2tf(pa1.z), f2tf(pa1.w));
        uint4 b0 = make_uint4(f2tf(pb0.x), f2tf(pb0.y), f2tf(pb0.z), f2tf(pb0.w));
        uint4 b1 = make_uint4(f2tf(pb1.x), f2tf(pb1.y), f2tf(pb1.z), f2tf(pb1.w));
        *(uint4*)&As[buf][ar * PA2 + ac]        = a0;
        *(uint4*)&As[buf][(ar + 64) * PA2 + ac] = a1;
        *(uint4*)&Bs[buf][br * PB + bc]         = b0;
        *(uint4*)&Bs[buf][(br + 8) * PB + bc]   = b1;
    };

    ldg(0);
    sts(0);
    __syncthreads();

    int buf = 0;
    for (int kt = 0; kt < KT; kt++) {
        if (kt + 1 < KT) ldg(kt + 1);

        #pragma unroll
        for (int ks = 0; ks < 2; ks++) {
            const int kb = ks * 8;
            uint32_t a[2][4];
            #pragma unroll
            for (int mt = 0; mt < 2; mt++) {
                int m = wr + mt * 16 + g;
                a[mt][0] = As[buf][m * PA2 + kb + tg];
                a[mt][1] = As[buf][(m + 8) * PA2 + kb + tg];
                a[mt][2] = As[buf][m * PA2 + kb + tg + 4];
                a[mt][3] = As[buf][(m + 8) * PA2 + kb + tg + 4];
            }
            #pragma unroll
            for (int nt = 0; nt < 8; nt++) {
                uint32_t b[2];
                int n = wc + nt * 8 + g;
                b[0] = Bs[buf][(kb + tg) * PB + n];
                b[1] = Bs[buf][(kb + tg + 4) * PB + n];
                MMA_TF32(acc[0][nt], a[0], b);
                MMA_TF32(acc[1][nt], a[1], b);
            }
        }
        if (kt + 1 < KT) sts(buf ^ 1);
        __syncthreads();
        buf ^= 1;
    }

    #pragma unroll
    for (int mt = 0; mt < 2; mt++) {
        #pragma unroll
        for (int nt = 0; nt < 8; nt++) {
            int row = rowBase + wr + mt * 16 + g;
            int col = colBase + wc + nt * 8 + 2 * tg;
            float2 bv = *(const float2*)&bias[col];
            float2 r0 = make_float2(acc[mt][nt][0] + bv.x, acc[mt][nt][1] + bv.y);
            float2 r1 = make_float2(acc[mt][nt][2] + bv.x, acc[mt][nt][3] + bv.y);
            *(float2*)&C[(size_t)row * N + col]       = r0;
            *(float2*)&C[(size_t)(row + 8) * N + col] = r1;
        }
    }
}

// Fused Q/K/V projections: blockIdx.z selects which GEMM.
__global__ void __launch_bounds__(256) gemm_qkv_kernel(
    const float* __restrict__ query, const float* __restrict__ context,
    const float* __restrict__ Wq, const float* __restrict__ bq,
    const float* __restrict__ Wk, const float* __restrict__ bk,
    const float* __restrict__ Wv, const float* __restrict__ bv,
    float* __restrict__ pQ, float* __restrict__ pK, float* __restrict__ pV)
{
    const int z = blockIdx.z;
    const float* A    = (z == 0) ? query : context;
    const float* W    = (z == 0) ? Wq : (z == 1) ? Wk : Wv;
    const float* bias = (z == 0) ? bq : (z == 1) ? bk : bv;
    float* C          = (z == 0) ? pQ : (z == 1) ? pK : pV;
    gemm_body(A, W, bias, C, blockIdx.x, blockIdx.y);
}

__global__ void __launch_bounds__(256) gemm_o_kernel(
    const float* __restrict__ A, const float* __restrict__ W,
    const float* __restrict__ bias, float* __restrict__ C)
{
    gemm_body(A, W, bias, C, blockIdx.x, blockIdx.y);
}

// ---------------------------------------------------------------------------
// Flash attention, tf32 mma.sync. q-tile 128 rows, 4 warps (32 rows each),
// Q fragments in registers; K/V double-buffered in smem; software-pipelined
// global prefetch; ONE __syncthreads per k-tile.
// ---------------------------------------------------------------------------
#define FPW 68
// smem: Ks[2][64*FPW] | Vs[2][64*FPW] | Ps[128*FPW]  = 384*FPW u32 = 104448 B
#define FSM_TOTAL (384 * FPW * 4)

__global__ void __launch_bounds__(128) flash_mma_kernel(
    const float* __restrict__ Qm, const float* __restrict__ Km,
    const float* __restrict__ Vm, float* __restrict__ Om)
{
    extern __shared__ uint32_t sm[];
    uint32_t* Ks = sm;                      // 2 buffers
    uint32_t* Vs = sm + 2 * 64 * FPW;       // 2 buffers
    uint32_t* Ps = sm + 4 * 64 * FPW;       // [128][FPW]

    const int b  = blockIdx.z;
    const int h  = blockIdx.y;
    const int q0 = blockIdx.x * 128;
    const int tid  = threadIdx.x;
    const int lane = tid & 31;
    const int warp = tid >> 5;
    const int g    = lane >> 2;
    const int tg   = lane & 3;
    const int mrow = warp * 32;
    const float scale = 0.125f;

    const float* Qbase = Qm + ((size_t)b * QLEN) * EMBED + h * HDIM;
    const float* Kbase = Km + ((size_t)b * CLEN) * EMBED + h * HDIM;
    const float* Vbase = Vm + ((size_t)b * CLEN) * EMBED + h * HDIM;

    // per-thread tile-load coords (64 rows x 64 cols, 128 threads, 8 float4 each)
    const int lr = tid >> 4;           // rows lr + 8*i
    const int lc = (tid & 15) * 4;     // col (floats)

    float4 pf[8];   // prefetch staging (reused for K then V)
    auto ldgK = [&](int kt) {
        const float* base = Kbase + (size_t)(kt * 64 + lr) * EMBED + lc;
        #pragma unroll
        for (int i = 0; i < 8; i++)
            pf[i] = *(const float4*)(base + (size_t)(8 * i) * EMBED);
    };
    auto ldgV = [&](int kt) {
        const float* base = Vbase + (size_t)(kt * 64 + lr) * EMBED + lc;
        #pragma unroll
        for (int i = 0; i < 8; i++)
            pf[i] = *(const float4*)(base + (size_t)(8 * i) * EMBED);
    };
    auto stsT = [&](uint32_t* dst) {
        #pragma unroll
        for (int i = 0; i < 8; i++) {
            uint4 t = make_uint4(f2tf(pf[i].x), f2tf(pf[i].y),
                                 f2tf(pf[i].z), f2tf(pf[i].w));
            *(uint4*)&dst[(lr + 8 * i) * FPW + lc] = t;
        }
    };

    // Stage Q (scaled, tf32) into Ps
    #pragma unroll
    for (int i = 0; i < 16; i++) {
        int idx = tid + i * 128;
        int r = idx >> 4;
        int c = (idx & 15) * 4;
        float4 v = *(const float4*)&Qbase[(size_t)(q0 + r) * EMBED + c];
        uint4 t = make_uint4(f2tf(v.x * scale), f2tf(v.y * scale),
                             f2tf(v.z * scale), f2tf(v.w * scale));
        *(uint4*)&Ps[r * FPW + c] = t;
    }
    ldgK(0);
    __syncthreads();

    // Q fragments -> registers
    uint32_t qf[2][8][4];
    #pragma unroll
    for (int mt = 0; mt < 2; mt++) {
        int m = mrow + mt * 16 + g;
        #pragma unroll
        for (int ks = 0; ks < 8; ks++) {
            int kb = ks * 8;
            qf[mt][ks][0] = Ps[m * FPW + kb + tg];
            qf[mt][ks][1] = Ps[(m + 8) * FPW + kb + tg];
            qf[mt][ks][2] = Ps[m * FPW + kb + tg + 4];
            qf[mt][ks][3] = Ps[(m + 8) * FPW + kb + tg + 4];
        }
    }
    stsT(Ks);          // K tile 0 -> buf 0
    ldgV(0);
    stsT(Vs);          // V tile 0 -> buf 0
    __syncthreads();

    float m_[4], l_[4];
    #pragma unroll
    for (int i = 0; i < 4; i++) { m_[i] = -INFINITY; l_[i] = 0.f; }
    float o[2][8][4];
    #pragma unroll
    for (int mt = 0; mt < 2; mt++)
        #pragma unroll
        for (int nt = 0; nt < 8; nt++)
            #pragma unroll
            for (int e = 0; e < 4; e++) o[mt][nt][e] = 0.f;

    const int NT = CLEN / 64;
    for (int kt = 0; kt < NT; kt++) {
        const int buf = kt & 1;
        uint32_t* Kcur = Ks + buf * 64 * FPW;
        uint32_t* Vcur = Vs + buf * 64 * FPW;
        uint32_t* Knxt = Ks + (buf ^ 1) * 64 * FPW;
        uint32_t* Vnxt = Vs + (buf ^ 1) * 64 * FPW;

        if (kt + 1 < NT) ldgK(kt + 1);   // overlap with S-MMA

        // ---- S = Q K^T ----
        float sacc[2][8][4];
        #pragma unroll
        for (int mt = 0; mt < 2; mt++)
            #pragma unroll
            for (int nt = 0; nt < 8; nt++)
                #pragma unroll
                for (int e = 0; e < 4; e++) sacc[mt][nt][e] = 0.f;

        #pragma unroll
        for (int ks = 0; ks < 8; ks++) {
            const int kb = ks * 8;
            #pragma unroll
            for (int nt = 0; nt < 8; nt++) {
                uint32_t bf[2];
                bf[0] = Kcur[(nt * 8 + g) * FPW + kb + tg];
                bf[1] = Kcur[(nt * 8 + g) * FPW + kb + tg + 4];
                MMA_TF32(sacc[0][nt], qf[0][ks], bf);
                MMA_TF32(sacc[1][nt], qf[1][ks], bf);
            }
        }

        if (kt + 1 < NT) {
            stsT(Knxt);
            ldgV(kt + 1);   // overlap with softmax + PV
        }

        // ---- online softmax ----
        #pragma unroll
        for (int mt = 0; mt < 2; mt++) {
            float mx0 = -INFINITY, mx1 = -INFINITY;
            #pragma unroll
            for (int nt = 0; nt < 8; nt++) {
                mx0 = fmaxf(mx0, fmaxf(sacc[mt][nt][0], sacc[mt][nt][1]));
                mx1 = fmaxf(mx1, fmaxf(sacc[mt][nt][2], sacc[mt][nt][3]));
            }
            #pragma unroll
            for (int off = 1; off < 4; off <<= 1) {
                mx0 = fmaxf(mx0, __shfl_xor_sync(0xffffffffu, mx0, off));
                mx1 = fmaxf(mx1, __shfl_xor_sync(0xffffffffu, mx1, off));
            }
            float mn0 = fmaxf(m_[2 * mt],     mx0);
            float mn1 = fmaxf(m_[2 * mt + 1], mx1);
            float c0 = __expf(m_[2 * mt]     - mn0);
            float c1 = __expf(m_[2 * mt + 1] - mn1);

            float rs0 = 0.f, rs1 = 0.f;
            int m = mrow + mt * 16 + g;
            #pragma unroll
            for (int nt = 0; nt < 8; nt++) {
                float p00 = __expf(sacc[mt][nt][0] - mn0);
                float p01 = __expf(sacc[mt][nt][1] - mn0);
                float p10 = __expf(sacc[mt][nt][2] - mn1);
                float p11 = __expf(sacc[mt][nt][3] - mn1);
                rs0 += p00 + p01;
                rs1 += p10 + p11;
                int col = nt * 8 + 2 * tg;
                *(uint2*)&Ps[m * FPW + col]       = make_uint2(f2tf(p00), f2tf(p01));
                *(uint2*)&Ps[(m + 8) * FPW + col] = make_uint2(f2tf(p10), f2tf(p11));
            }
            #pragma unroll
            for (int off = 1; off < 4; off <<= 1) {
                rs0 += __shfl_xor_sync(0xffffffffu, rs0, off);
                rs1 += __shfl_xor_sync(0xffffffffu, rs1, off);
            }
            l_[2 * mt]     = l_[2 * mt]     * c0 + rs0;
            l_[2 * mt + 1] = l_[2 * mt + 1] * c1 + rs1;
            m_[2 * mt]     = mn0;
            m_[2 * mt + 1] = mn1;
            #pragma unroll
            for (int nt = 0; nt < 8; nt++) {
                o[mt][nt][0] *= c0; o[mt][nt][1] *= c0;
                o[mt][nt][2] *= c1; o[mt][nt][3] *= c1;
            }
        }
        __syncwarp();   // own P rows visible within warp

        // ---- O += P V ----
        #pragma unroll
        for (int ks = 0; ks < 8; ks++) {
            const int kb = ks * 8;
            uint32_t af[2][4];
            #pragma unroll
            for (int mt = 0; mt < 2; mt++) {
                int m = mrow + mt * 16 + g;
                af[mt][0] = Ps[m * FPW + kb + tg];
                af[mt][1] = Ps[(m + 8) * FPW + kb + tg];
                af[mt][2] = Ps[m * FPW + kb + tg + 4];
                af[mt][3] = Ps[(m + 8) * FPW + kb + tg + 4];
            }
            #pragma unroll
            for (int nt = 0; nt < 8; nt++) {
                uint32_t bf[2];
                bf[0] = Vcur[(kb + tg) * FPW + nt * 8 + g];
                bf[1] = Vcur[(kb + tg + 4) * FPW + nt * 8 + g];
                MMA_TF32(o[0][nt], af[0], bf);
                MMA_TF32(o[1][nt], af[1], bf);
            }
        }

        if (kt + 1 < NT) stsT(Vnxt);
        __syncthreads();   // buffers flip: all reads of cur done, nxt fully written
    }

    // normalize + write
    #pragma unroll
    for (int mt = 0; mt < 2; mt++) {
        float i0 = 1.f / l_[2 * mt];
        float i1 = 1.f / l_[2 * mt + 1];
        int r0 = q0 + mrow + mt * 16 + g;
        #pragma unroll
        for (int nt = 0; nt < 8; nt++) {
            int col = h * HDIM + nt * 8 + 2 * tg;
            float2 w0 = make_float2(o[mt][nt][0] * i0, o[mt][nt][1] * i0);
            float2 w1 = make_float2(o[mt][nt][2] * i1, o[mt][nt][3] * i1);
            *(float2*)&Om[((size_t)b * QLEN + r0) * EMBED + col]     = w0;
            *(float2*)&Om[((size_t)b * QLEN + r0 + 8) * EMBED + col] = w1;
        }
    }
}

// ---------------------------------------------------------------------------
extern "C" void kernel_launch(void* const* d_in, const int* in_sizes, int n_in,
                              void* d_out, int out_size)
{
    const float* query   = (const float*)d_in[0];
    const float* context = (const float*)d_in[1];
    const float* Wq = (const float*)d_in[2];
    const float* bq = (const float*)d_in[3];
    const float* Wk = (const float*)d_in[4];
    const float* bk = (const float*)d_in[5];
    const float* Wv = (const float*)d_in[6];
    const float* bv = (const float*)d_in[7];
    const float* Wo = (const float*)d_in[8];
    const float* bo = (const float*)d_in[9];
    float* out = (float*)d_out;

    float *pQ, *pK, *pV, *pA;
    cudaGetSymbolAddress((void**)&pQ, g_Q);
    cudaGetSymbolAddress((void**)&pK, g_K);
    cudaGetSymbolAddress((void**)&pV, g_V);
    cudaGetSymbolAddress((void**)&pA, g_A);

    // fused QKV projections: one launch, grid (8, 32, 3)
    dim3 gQKV(EMBED / 128, MROWS / 128, 3);
    gemm_qkv_kernel<<<gQKV, 256>>>(query, context, Wq, bq, Wk, bk, Wv, bv,
                                   pQ, pK, pV);

    cudaFuncSetAttribute(flash_mma_kernel,
                         cudaFuncAttributeMaxDynamicSharedMemorySize, FSM_TOTAL);
    flash_mma_kernel<<<dim3(QLEN / 128, NHEADS, BATCH), 128, FSM_TOTAL>>>(pQ, pK, pV, pA);

    dim3 gGemm(EMBED / 128, MROWS / 128);
    gemm_o_kernel<<<gGemm, 256>>>(pA, Wo, bo, out);
}

// round 6
// speedup vs baseline: 7.3035x; 1.6766x over previous
#include <cuda_runtime.h>
#include <math.h>
#include <stdint.h>

#define EMBED   1024
#define NHEADS  16
#define HDIM    64
#define BATCH   2
#define QLEN    2048
#define CLEN    2048
#define MROWS   (BATCH * QLEN)   // 4096
#define KP      (EMBED / 2)      // 512 u32 pairs per row

// Scratch: fp16 pair-packed tensors (u32 = 2 half). Total 64MB.
__device__ uint32_t g_Xqh[MROWS * KP];        // query fp16-packed
__device__ uint32_t g_Xch[MROWS * KP];        // context fp16-packed
__device__ uint32_t g_Wh[4][KP * EMBED];      // Wq,Wk,Wv,Wo packed [kp][n]
__device__ uint32_t g_Qh[MROWS * KP];         // Q*(1/8) fp16 [row][dp]
__device__ uint32_t g_Kh[MROWS * KP];         // K fp16 [row][dp]
__device__ float    g_Vf[MROWS * EMBED];      // V fp32
__device__ uint32_t g_Ah[MROWS * KP];         // attended fp16 [row][dp]

__device__ __forceinline__ uint32_t f2h2(float lo, float hi) {
    uint32_t r;
    asm("cvt.rn.f16x2.f32 %0, %1, %2;" : "=r"(r) : "f"(hi), "f"(lo));
    return r;
}

// D += A(16x16) * B(16x8), fp16 in, fp32 accum
#define MMA_F16(d, a, b)                                                   \
    asm volatile(                                                          \
        "mma.sync.aligned.m16n8k16.row.col.f32.f16.f16.f32 "               \
        "{%0,%1,%2,%3}, {%4,%5,%6,%7}, {%8,%9}, {%0,%1,%2,%3};"            \
        : "+f"(d[0]), "+f"(d[1]), "+f"(d[2]), "+f"(d[3])                   \
        : "r"(a[0]), "r"(a[1]), "r"(a[2]), "r"(a[3]), "r"(b[0]), "r"(b[1]))

// ---------------------------------------------------------------------------
// Prepass: pack fp32 -> fp16 pairs. z=0 query, z=1 context, z=2..5 weights.
// X pack: pairs along row (contiguous). W pack: pairs along k (rows), [kp][n].
// ---------------------------------------------------------------------------
__global__ void __launch_bounds__(256) prepack_kernel(
    const float* __restrict__ q, const float* __restrict__ ctx,
    const float* __restrict__ Wq, const float* __restrict__ Wk,
    const float* __restrict__ Wv, const float* __restrict__ Wo)
{
    const int z = blockIdx.z;
    const int stride = gridDim.x * blockDim.x;
    int i0 = blockIdx.x * blockDim.x + threadIdx.x;

    if (z < 2) {
        const float* src = (z == 0) ? q : ctx;
        uint2* dst = (uint2*)((z == 0) ? g_Xqh : g_Xch);
        const int count = MROWS * KP / 2;   // uint2 units (float4 in)
        for (int i = i0; i < count; i += stride) {
            float4 v = ((const float4*)src)[i];
            dst[i] = make_uint2(f2h2(v.x, v.y), f2h2(v.z, v.w));
        }
    } else {
        const float* W = (z == 2) ? Wq : (z == 3) ? Wk : (z == 4) ? Wv : Wo;
        uint4* dst = (uint4*)g_Wh[z - 2];
        const int count = KP * EMBED / 4;   // uint4 units
        for (int i = i0; i < count; i += stride) {
            int kp = i >> 8;                // 1024/4 = 256 uint4 per kp row
            int n4 = (i & 255) * 4;
            float4 a = *(const float4*)&W[(size_t)(2 * kp) * EMBED + n4];
            float4 b = *(const float4*)&W[(size_t)(2 * kp + 1) * EMBED + n4];
            dst[i] = make_uint4(f2h2(a.x, b.x), f2h2(a.y, b.y),
                                f2h2(a.z, b.z), f2h2(a.w, b.w));
        }
    }
}

// ---------------------------------------------------------------------------
// fp16 GEMM + bias: C[4096,1024] = A @ W + b.  A,[4096][512]u32  W,[512][1024]u32
// CTA 128x128, BK=16 (one m16n8k16 step per slab), double-buffered,
// 256 threads, warp tile 32x64.
// outHalf=1: write fp16 pairs (scale applied after bias); else fp32.
// ---------------------------------------------------------------------------
#define PAH 12    // A smem pitch (u32): 8 kp + 4 pad
#define PBH 136   // B smem pitch

__device__ __forceinline__ void gemm_h_body(
    const uint32_t* __restrict__ A, const uint32_t* __restrict__ W,
    const float* __restrict__ bias, void* __restrict__ Cout,
    int outHalf, float oscale, int bx, int by)
{
    __shared__ uint32_t As[2][128 * PAH];
    __shared__ uint32_t Bs[2][8 * PBH];

    const int tid  = threadIdx.x;
    const int lane = tid & 31;
    const int warp = tid >> 5;
    const int g    = lane >> 2;
    const int tg   = lane & 3;
    const int wr   = (warp >> 1) * 32;
    const int wc   = (warp & 1) * 64;
    const int rowBase = by * 128;
    const int colBase = bx * 128;

    const int am  = tid >> 1;          // A row 0..127
    const int akp = (tid & 1) * 4;     // kp 0 or 4
    const int bkp = tid >> 5;          // B kp row 0..7
    const int bn  = (tid & 31) * 4;    // n

    const uint32_t* Aptr = A + (size_t)(rowBase + am) * KP + akp;
    const uint32_t* Wptr = W + (size_t)bkp * EMBED + colBase + bn;

    float acc[2][8][4];
    #pragma unroll
    for (int mt = 0; mt < 2; mt++)
        #pragma unroll
        for (int nt = 0; nt < 8; nt++)
            #pragma unroll
            for (int e = 0; e < 4; e++) acc[mt][nt][e] = 0.f;

    uint4 ra, rb;
    auto ldg = [&](int kt) {
        ra = *(const uint4*)(Aptr + kt * 8);
        rb = *(const uint4*)(Wptr + (size_t)(kt * 8) * EMBED);
    };
    auto sts = [&](int buf) {
        *(uint4*)&As[buf][am * PAH + akp] = ra;
        *(uint4*)&Bs[buf][bkp * PBH + bn] = rb;
    };

    ldg(0);
    sts(0);
    __syncthreads();

    int buf = 0;
    for (int kt = 0; kt < 64; kt++) {
        if (kt + 1 < 64) ldg(kt + 1);

        uint32_t a[2][4];
        #pragma unroll
        for (int mt = 0; mt < 2; mt++) {
            int m = wr + mt * 16 + g;
            a[mt][0] = As[buf][m * PAH + tg];
            a[mt][1] = As[buf][(m + 8) * PAH + tg];
            a[mt][2] = As[buf][m * PAH + tg + 4];
            a[mt][3] = As[buf][(m + 8) * PAH + tg + 4];
        }
        #pragma unroll
        for (int nt = 0; nt < 8; nt++) {
            uint32_t b[2];
            int n = wc + nt * 8 + g;
            b[0] = Bs[buf][tg * PBH + n];
            b[1] = Bs[buf][(tg + 4) * PBH + n];
            MMA_F16(acc[0][nt], a[0], b);
            MMA_F16(acc[1][nt], a[1], b);
        }
        if (kt + 1 < 64) sts(buf ^ 1);
        __syncthreads();
        buf ^= 1;
    }

    if (outHalf) {
        uint32_t* C = (uint32_t*)Cout;
        #pragma unroll
        for (int mt = 0; mt < 2; mt++) {
            #pragma unroll
            for (int nt = 0; nt < 8; nt++) {
                int row  = rowBase + wr + mt * 16 + g;
                int col  = colBase + wc + nt * 8 + 2 * tg;
                int colp = col >> 1;
                float2 bv = *(const float2*)&bias[col];
                C[(size_t)row * KP + colp] =
                    f2h2((acc[mt][nt][0] + bv.x) * oscale,
                         (acc[mt][nt][1] + bv.y) * oscale);
                C[(size_t)(row + 8) * KP + colp] =
                    f2h2((acc[mt][nt][2] + bv.x) * oscale,
                         (acc[mt][nt][3] + bv.y) * oscale);
            }
        }
    } else {
        float* C = (float*)Cout;
        #pragma unroll
        for (int mt = 0; mt < 2; mt++) {
            #pragma unroll
            for (int nt = 0; nt < 8; nt++) {
                int row = rowBase + wr + mt * 16 + g;
                int col = colBase + wc + nt * 8 + 2 * tg;
                float2 bv = *(const float2*)&bias[col];
                float2 r0 = make_float2(acc[mt][nt][0] + bv.x, acc[mt][nt][1] + bv.y);
                float2 r1 = make_float2(acc[mt][nt][2] + bv.x, acc[mt][nt][3] + bv.y);
                *(float2*)&C[(size_t)row * EMBED + col]       = r0;
                *(float2*)&C[(size_t)(row + 8) * EMBED + col] = r1;
            }
        }
    }
}

__global__ void __launch_bounds__(256) gemm_qkv_kernel(
    const float* __restrict__ bq, const float* __restrict__ bk,
    const float* __restrict__ bv)
{
    const int z = blockIdx.z;
    if (z == 0)      gemm_h_body(g_Xqh, g_Wh[0], bq, g_Qh, 1, 0.125f, blockIdx.x, blockIdx.y);
    else if (z == 1) gemm_h_body(g_Xch, g_Wh[1], bk, g_Kh, 1, 1.0f,   blockIdx.x, blockIdx.y);
    else             gemm_h_body(g_Xch, g_Wh[2], bv, g_Vf, 0, 1.0f,   blockIdx.x, blockIdx.y);
}

__global__ void __launch_bounds__(256) gemm_o_kernel(
    const float* __restrict__ bo, float* __restrict__ out)
{
    gemm_h_body(g_Ah, g_Wh[3], bo, out, 0, 1.0f, blockIdx.x, blockIdx.y);
}

// ---------------------------------------------------------------------------
// Flash attention fp16. q-tile 128, 4 warps x 32 rows; kv tiles of 64.
// Q (pre-scaled fp16 pairs) frags in regs; K fp16 pairs [kv][dp];
// V fp32 -> packed kv-pairs [kvp][d]; P packed kv-pairs [m][kvp].
// Double-buffered K/V, one barrier per tile. Output fp16 pairs to g_Ah.
// ---------------------------------------------------------------------------
#define PKH 36   // Ks pitch (u32): 32 dp + 4
#define PVH 72   // Vs pitch: 64 d + 8
#define PPH 36   // Ps pitch: 32 kvp/dp + 4
// smem: Ks[2][64*36] + Vs[2][32*72] + Ps[128*36] = 13824 u32 = 55296 B
#define FSM_TOTAL (13824 * 4)

__global__ void __launch_bounds__(128) flash_h_kernel()
{
    extern __shared__ uint32_t sm[];
    uint32_t* Ks = sm;                    // 2 x [64][PKH]
    uint32_t* Vs = sm + 2 * 64 * PKH;     // 2 x [32][PVH]
    uint32_t* Ps = sm + 2 * 64 * PKH + 2 * 32 * PVH;   // [128][PPH]

    const int b  = blockIdx.z;
    const int h  = blockIdx.y;
    const int q0 = blockIdx.x * 128;
    const int tid  = threadIdx.x;
    const int lane = tid & 31;
    const int warp = tid >> 5;
    const int g    = lane >> 2;
    const int tg   = lane & 3;
    const int mrow = warp * 32;

    const uint32_t* Qb = g_Qh + (size_t)b * QLEN * KP + h * 32;
    const uint32_t* Kb = g_Kh + (size_t)b * CLEN * KP + h * 32;
    const float*    Vb = g_Vf + (size_t)b * CLEN * EMBED + h * HDIM;

    // K loader: 64 rows x 32 dp u32
    const int kvr = tid >> 3;            // 0..15, rows kvr+16i
    const int dq  = (tid & 7) * 4;
    uint4 kpf[4];
    auto ldgK = [&](int kt) {
        #pragma unroll
        for (int i = 0; i < 4; i++)
            kpf[i] = *(const uint4*)&Kb[(size_t)(kt * 64 + kvr + 16 * i) * KP + dq];
    };
    auto stsK = [&](uint32_t* dst) {
        #pragma unroll
        for (int i = 0; i < 4; i++)
            *(uint4*)&dst[(kvr + 16 * i) * PKH + dq] = kpf[i];
    };

    // V loader: 64 rows x 64 d fp32 -> [32 kvp][64 d] u32 pairs
    const int va_ = tid >> 4;            // 0..7, kvp rows va_+8i
    const int dcol = (tid & 15) * 4;
    float4 vpa[4], vpb[4];
    auto ldgV = [&](int kt) {
        #pragma unroll
        for (int i = 0; i < 4; i++) {
            int kv2 = kt * 64 + 2 * (va_ + 8 * i);
            vpa[i] = *(const float4*)&Vb[(size_t)kv2 * EMBED + dcol];
            vpb[i] = *(const float4*)&Vb[(size_t)(kv2 + 1) * EMBED + dcol];
        }
    };
    auto stsV = [&](uint32_t* dst) {
        #pragma unroll
        for (int i = 0; i < 4; i++) {
            uint4 u = make_uint4(f2h2(vpa[i].x, vpb[i].x), f2h2(vpa[i].y, vpb[i].y),
                                 f2h2(vpa[i].z, vpb[i].z), f2h2(vpa[i].w, vpb[i].w));
            *(uint4*)&dst[(va_ + 8 * i) * PVH + dcol] = u;
        }
    };

    // Stage Q tile into Ps: 128 rows x 32 dp
    #pragma unroll
    for (int i = 0; i < 8; i++) {
        int idx = tid + i * 128;
        int r = idx >> 3;
        int q4 = (idx & 7) * 4;
        uint4 v = *(const uint4*)&Qb[(size_t)(q0 + r) * KP + q4];
        *(uint4*)&Ps[r * PPH + q4] = v;
    }
    ldgK(0);
    __syncthreads();

    // Q fragments -> registers (4 k16 slabs over d)
    uint32_t qf[2][4][4];
    #pragma unroll
    for (int mt = 0; mt < 2; mt++) {
        int m = mrow + mt * 16 + g;
        #pragma unroll
        for (int s = 0; s < 4; s++) {
            qf[mt][s][0] = Ps[m * PPH + 8 * s + tg];
            qf[mt][s][1] = Ps[(m + 8) * PPH + 8 * s + tg];
            qf[mt][s][2] = Ps[m * PPH + 8 * s + tg + 4];
            qf[mt][s][3] = Ps[(m + 8) * PPH + 8 * s + tg + 4];
        }
    }
    stsK(Ks);
    ldgV(0);
    stsV(Vs);
    __syncthreads();

    float m_[4], l_[4];
    #pragma unroll
    for (int i = 0; i < 4; i++) { m_[i] = -INFINITY; l_[i] = 0.f; }
    float o[2][8][4];
    #pragma unroll
    for (int mt = 0; mt < 2; mt++)
        #pragma unroll
        for (int nt = 0; nt < 8; nt++)
            #pragma unroll
            for (int e = 0; e < 4; e++) o[mt][nt][e] = 0.f;

    const int NT = CLEN / 64;
    for (int kt = 0; kt < NT; kt++) {
        const int buf = kt & 1;
        uint32_t* Kcur = Ks + buf * 64 * PKH;
        uint32_t* Vcur = Vs + buf * 32 * PVH;
        uint32_t* Knxt = Ks + (buf ^ 1) * 64 * PKH;
        uint32_t* Vnxt = Vs + (buf ^ 1) * 32 * PVH;

        if (kt + 1 < NT) ldgK(kt + 1);

        // ---- S = Q K^T ----
        float sacc[2][8][4];
        #pragma unroll
        for (int mt = 0; mt < 2; mt++)
            #pragma unroll
            for (int nt = 0; nt < 8; nt++)
                #pragma unroll
                for (int e = 0; e < 4; e++) sacc[mt][nt][e] = 0.f;

        #pragma unroll
        for (int s = 0; s < 4; s++) {
            #pragma unroll
            for (int nt = 0; nt < 8; nt++) {
                uint32_t bf[2];
                bf[0] = Kcur[(nt * 8 + g) * PKH + 8 * s + tg];
                bf[1] = Kcur[(nt * 8 + g) * PKH + 8 * s + tg + 4];
                MMA_F16(sacc[0][nt], qf[0][s], bf);
                MMA_F16(sacc[1][nt], qf[1][s], bf);
            }
        }

        if (kt + 1 < NT) {
            stsK(Knxt);
            ldgV(kt + 1);
        }

        // ---- online softmax; P -> Ps as fp16 kv-pairs ----
        #pragma unroll
        for (int mt = 0; mt < 2; mt++) {
            float mx0 = -INFINITY, mx1 = -INFINITY;
            #pragma unroll
            for (int nt = 0; nt < 8; nt++) {
                mx0 = fmaxf(mx0, fmaxf(sacc[mt][nt][0], sacc[mt][nt][1]));
                mx1 = fmaxf(mx1, fmaxf(sacc[mt][nt][2], sacc[mt][nt][3]));
            }
            #pragma unroll
            for (int off = 1; off < 4; off <<= 1) {
                mx0 = fmaxf(mx0, __shfl_xor_sync(0xffffffffu, mx0, off));
                mx1 = fmaxf(mx1, __shfl_xor_sync(0xffffffffu, mx1, off));
            }
            float mn0 = fmaxf(m_[2 * mt],     mx0);
            float mn1 = fmaxf(m_[2 * mt + 1], mx1);
            float c0 = __expf(m_[2 * mt]     - mn0);
            float c1 = __expf(m_[2 * mt + 1] - mn1);

            float rs0 = 0.f, rs1 = 0.f;
            int m = mrow + mt * 16 + g;
            #pragma unroll
            for (int nt = 0; nt < 8; nt++) {
                float p00 = __expf(sacc[mt][nt][0] - mn0);
                float p01 = __expf(sacc[mt][nt][1] - mn0);
                float p10 = __expf(sacc[mt][nt][2] - mn1);
                float p11 = __expf(sacc[mt][nt][3] - mn1);
                rs0 += p00 + p01;
                rs1 += p10 + p11;
                Ps[m * PPH + nt * 4 + tg]       = f2h2(p00, p01);
                Ps[(m + 8) * PPH + nt * 4 + tg] = f2h2(p10, p11);
            }
            #pragma unroll
            for (int off = 1; off < 4; off <<= 1) {
                rs0 += __shfl_xor_sync(0xffffffffu, rs0, off);
                rs1 += __shfl_xor_sync(0xffffffffu, rs1, off);
            }
            l_[2 * mt]     = l_[2 * mt]     * c0 + rs0;
            l_[2 * mt + 1] = l_[2 * mt + 1] * c1 + rs1;
            m_[2 * mt]     = mn0;
            m_[2 * mt + 1] = mn1;
            #pragma unroll
            for (int nt = 0; nt < 8; nt++) {
                o[mt][nt][0] *= c0; o[mt][nt][1] *= c0;
                o[mt][nt][2] *= c1; o[mt][nt][3] *= c1;
            }
        }
        __syncwarp();

        // ---- O += P V ----
        #pragma unroll
        for (int s = 0; s < 4; s++) {
            uint32_t af[2][4];
            #pragma unroll
            for (int mt = 0; mt < 2; mt++) {
                int m = mrow + mt * 16 + g;
                af[mt][0] = Ps[m * PPH + 8 * s + tg];
                af[mt][1] = Ps[(m + 8) * PPH + 8 * s + tg];
                af[mt][2] = Ps[m * PPH + 8 * s + tg + 4];
                af[mt][3] = Ps[(m + 8) * PPH + 8 * s + tg + 4];
            }
            #pragma unroll
            for (int nt = 0; nt < 8; nt++) {
                uint32_t bf[2];
                bf[0] = Vcur[(8 * s + tg) * PVH + nt * 8 + g];
                bf[1] = Vcur[(8 * s + tg + 4) * PVH + nt * 8 + g];
                MMA_F16(o[0][nt], af[0], bf);
                MMA_F16(o[1][nt], af[1], bf);
            }
        }

        if (kt + 1 < NT) stsV(Vnxt);
        __syncthreads();
    }

    // normalize + write fp16 pairs to g_Ah [row][h*32 + nt*4 + tg]
    uint32_t* Ab = g_Ah + (size_t)b * QLEN * KP + h * 32;
    #pragma unroll
    for (int mt = 0; mt < 2; mt++) {
        float i0 = 1.f / l_[2 * mt];
        float i1 = 1.f / l_[2 * mt + 1];
        int r0 = q0 + mrow + mt * 16 + g;
        #pragma unroll
        for (int nt = 0; nt < 8; nt++) {
            int colp = nt * 4 + tg;
            Ab[(size_t)r0 * KP + colp]       = f2h2(o[mt][nt][0] * i0, o[mt][nt][1] * i0);
            Ab[(size_t)(r0 + 8) * KP + colp] = f2h2(o[mt][nt][2] * i1, o[mt][nt][3] * i1);
        }
    }
}

// ---------------------------------------------------------------------------
extern "C" void kernel_launch(void* const* d_in, const int* in_sizes, int n_in,
                              void* d_out, int out_size)
{
    const float* query   = (const float*)d_in[0];
    const float* context = (const float*)d_in[1];
    const float* Wq = (const float*)d_in[2];
    const float* bq = (const float*)d_in[3];
    const float* Wk = (const float*)d_in[4];
    const float* bk = (const float*)d_in[5];
    const float* Wv = (const float*)d_in[6];
    const float* bv = (const float*)d_in[7];
    const float* Wo = (const float*)d_in[8];
    const float* bo = (const float*)d_in[9];
    float* out = (float*)d_out;

    // 1) pack inputs + weights to fp16 pairs
    prepack_kernel<<<dim3(256, 1, 6), 256>>>(query, context, Wq, Wk, Wv, Wo);

    // 2) fused QKV projections (Q scaled by 1/8, Q/K fp16, V fp32)
    dim3 gQKV(EMBED / 128, MROWS / 128, 3);
    gemm_qkv_kernel<<<gQKV, 256>>>(bq, bk, bv);

    // 3) flash attention (fp16 mma, fp32 softmax), writes fp16 attended
    cudaFuncSetAttribute(flash_h_kernel,
                         cudaFuncAttributeMaxDynamicSharedMemorySize, FSM_TOTAL);
    flash_h_kernel<<<dim3(QLEN / 128, NHEADS, BATCH), 128, FSM_TOTAL>>>();

    // 4) output projection (fp32 out)
    dim3 gGemm(EMBED / 128, MROWS / 128);
    gemm_o_kernel<<<gGemm, 256>>>(bo, out);
}